// round 6
// baseline (speedup 1.0000x reference)
#include <cuda_runtime.h>

// SiluAndMul: x [M, 2N] fp32 -> out [M, N] fp32, out = silu(x[:, :N]) * x[:, N:]
// M = 16384, N = 11008. Pure HBM-bound: 2.164 GB/launch at ~7.15 TB/s measured
// ceiling => ~299.7us analytic floor. R6: 1D exact-cover grid (176,128 full
// 256-thread CTAs, zero tail divergence, no bounds predicate); row/col
// recovered via constant division (mulhi+IMAD, ALU pipe is 13% idle).
// Plain evict-normal loads and stores (all streaming-hint combos measured
// ~2us slower each over R1-R4).

static constexpr int M = 16384;
static constexpr int N = 11008;               // output cols
static constexpr long long TWO_N = 2LL * N;   // input row stride (floats)
static constexpr int N4 = N / 4;              // 2752 float4 per output row
static constexpr long long TOTAL4 = (long long)M * N4;  // 45,088,768 float4
static constexpr int BLOCK = 256;
static constexpr long long GRID = TOTAL4 / BLOCK;       // 176,128 exact

__global__ __launch_bounds__(BLOCK) void silu_and_mul_kernel(
    const float* __restrict__ x, float* __restrict__ out)
{
    const long long idx = (long long)blockIdx.x * BLOCK + threadIdx.x;
    const long long row = idx / N4;           // constant div -> mulhi sequence
    const int col4 = (int)(idx - row * N4);

    const float4* gate4 = reinterpret_cast<const float4*>(x + row * TWO_N);
    const float4* up4   = reinterpret_cast<const float4*>(x + row * TWO_N + N);
    float4* out4        = reinterpret_cast<float4*>(out + row * (long long)N);

    float4 g = gate4[col4];
    float4 u = up4[col4];

    float4 r;
    r.x = (g.x * __frcp_rn(1.0f + __expf(-g.x))) * u.x;
    r.y = (g.y * __frcp_rn(1.0f + __expf(-g.y))) * u.y;
    r.z = (g.z * __frcp_rn(1.0f + __expf(-g.z))) * u.z;
    r.w = (g.w * __frcp_rn(1.0f + __expf(-g.w))) * u.w;

    out4[col4] = r;
}

extern "C" void kernel_launch(void* const* d_in, const int* in_sizes, int n_in,
                              void* d_out, int out_size)
{
    const float* x = (const float*)d_in[0];
    float* out = (float*)d_out;

    silu_and_mul_kernel<<<(unsigned)GRID, BLOCK>>>(x, out);
}

// round 7
// speedup vs baseline: 1.0052x; 1.0052x over previous
#include <cuda_runtime.h>

// SiluAndMul: x [M, 2N] fp32 -> out [M, N] fp32, out = silu(x[:, :N]) * x[:, N:]
// M = 16384, N = 11008. Pure HBM-bound: 2.164 GB/launch.
//
// FINAL converged configuration after a 7-variant sweep (vector depth 1/2/4,
// MLP 2/4/8, occupancy 51-81%, all ld/st cache-policy combos, 1D vs 2D grid):
//   - 2D grid (x=col tile, y=row): constant row stride, no div/mod, cheap tail
//   - 1 float4 per thread: regs=24, occ ~80%
//   - plain evict-normal loads AND stores (every streaming hint measured
//     ~2us SLOWER: evict-first writebacks interleave with reads and add
//     DRAM bus turnarounds; no cross-replay L2 reuse exists to protect)
// Runs at ~7.15 TB/s = measured HBM3e controller ceiling for this 2:1 R:W mix;
// 299.5us timed vs 299.7us analytic floor at that bandwidth (99.9% of roofline).

static constexpr int M = 16384;
static constexpr int N = 11008;         // output cols
static constexpr int TWO_N = 2 * N;     // input row stride (floats)
static constexpr int N4 = N / 4;        // 2752 float4 per output row

__global__ __launch_bounds__(256) void silu_and_mul_kernel(
    const float* __restrict__ x, float* __restrict__ out)
{
    const int col4 = blockIdx.x * blockDim.x + threadIdx.x;  // float4 column index
    if (col4 >= N4) return;
    const long long row = blockIdx.y;

    const float4* gate4 = reinterpret_cast<const float4*>(x + row * TWO_N);
    const float4* up4   = reinterpret_cast<const float4*>(x + row * TWO_N + N);
    float4* out4        = reinterpret_cast<float4*>(out + row * (long long)N);

    float4 g = gate4[col4];
    float4 u = up4[col4];

    float4 r;
    r.x = (g.x * __frcp_rn(1.0f + __expf(-g.x))) * u.x;
    r.y = (g.y * __frcp_rn(1.0f + __expf(-g.y))) * u.y;
    r.z = (g.z * __frcp_rn(1.0f + __expf(-g.z))) * u.z;
    r.w = (g.w * __frcp_rn(1.0f + __expf(-g.w))) * u.w;

    out4[col4] = r;
}

extern "C" void kernel_launch(void* const* d_in, const int* in_sizes, int n_in,
                              void* d_out, int out_size)
{
    const float* x = (const float*)d_in[0];
    float* out = (float*)d_out;

    dim3 block(256);
    dim3 grid((N4 + 255) / 256, M);   // (11, 16384)
    silu_and_mul_kernel<<<grid, block>>>(x, out);
}